// round 12
// baseline (speedup 1.0000x reference)
#include <cuda_runtime.h>
#include <cuda_fp16.h>

#define NN 100000
#define NE 1600000
#define CAP 128
#define NF1 128
#define NH  64
#define NC  40

typedef unsigned long long ull;

// -------- scratch (device globals; no allocation allowed) --------
__device__ float  g_deg[NN];
__device__ int    g_cnt[NN];
__device__ int2   g_slot[(long long)NN * CAP];  // (src_row, float_bits(dinv[src]*w)); zero-init -> row 0 safe
__device__ __half g_h1h[(long long)NN * NH];    // fp16(x @ W1)
__device__ __half g_h2h[(long long)NN * NC];    // fp16(out1 @ W2)

// -------- packed f32x2 helpers --------
__device__ __forceinline__ ull pack2(float x, float y) {
    ull r;
    asm("mov.b64 %0, {%1, %2};" : "=l"(r) : "f"(x), "f"(y));
    return r;
}
__device__ __forceinline__ void fma2(ull& d, ull a, ull b) {
    asm("fma.rn.f32x2 %0, %1, %2, %0;" : "+l"(d) : "l"(a), "l"(b));
}
__device__ __forceinline__ float2 unpack2(ull v) {
    float2 f;
    asm("mov.b64 {%0, %1}, %2;" : "=f"(f.x), "=f"(f.y) : "l"(v));
    return f;
}

// -------- prep kernels --------
__global__ void k_init() {
    int n = blockIdx.x * blockDim.x + threadIdx.x;
    if (n < NN) { g_deg[n] = 1.0f; g_cnt[n] = 0; }  // self-loop weight 1
}

__global__ void k_deg(const int* __restrict__ ei, const float* __restrict__ ew) {
    int e = blockIdx.x * blockDim.x + threadIdx.x;
    if (e < NE) {
        int c = ei[NE + e];
        if (c >= 0 && c < NN) atomicAdd(&g_deg[c], ew[e]);
    }
}

__global__ void k_place(const int* __restrict__ ei, const float* __restrict__ ew) {
    int e = blockIdx.x * blockDim.x + threadIdx.x;
    if (e >= NE) return;
    int r = ei[e];
    int c = ei[NE + e];
    if (r < 0 || r >= NN || c < 0 || c >= NN) return;
    float dr = rsqrtf(g_deg[r]);          // deg >= 1 always (self loop)
    float pnorm = dr * ew[e];             // dinv[c] factored out; applied in gather epilogue
    int pos = atomicAdd(&g_cnt[c], 1);
    if (pos < CAP) {
        int2 s;
        s.x = r;
        s.y = __float_as_int(pnorm);
        g_slot[(long long)c * CAP + pos] = s;
    }
}

// -------- software-pipelined per-node gather --------
// Prefetches the NEXT group's 4x int4 slot words while h-loads of the current
// group are in flight. CAP-padded row => clamped prefetch index always in-bounds.
template<int STRIDE>
__device__ __forceinline__ float2 gather_node(const int2* __restrict__ slots, int c,
                                              const __half* __restrict__ h, int lane) {
    float2 acc = make_float2(0.f, 0.f);
    if (c <= 0) return acc;
    int4 sa = *(const int4*)&slots[0];
    int4 sb = *(const int4*)&slots[2];
    int4 sc = *(const int4*)&slots[4];
    int4 sd = *(const int4*)&slots[6];
    for (int kk = 0; kk < c; kk += 8) {
        int pk = (kk + 8 < c) ? kk + 8 : 0;     // branch-free, in-bounds
        const int4* nx = (const int4*)&slots[pk];
        int4 na = nx[0], nb = nx[1], nc_ = nx[2], nd = nx[3];
        __half2 v0 = *(const __half2*)&h[(long long)sa.x * STRIDE + lane * 2];
        __half2 v1 = *(const __half2*)&h[(long long)sa.z * STRIDE + lane * 2];
        __half2 v2 = *(const __half2*)&h[(long long)sb.x * STRIDE + lane * 2];
        __half2 v3 = *(const __half2*)&h[(long long)sb.z * STRIDE + lane * 2];
        __half2 v4 = *(const __half2*)&h[(long long)sc.x * STRIDE + lane * 2];
        __half2 v5 = *(const __half2*)&h[(long long)sc.z * STRIDE + lane * 2];
        __half2 v6 = *(const __half2*)&h[(long long)sd.x * STRIDE + lane * 2];
        __half2 v7 = *(const __half2*)&h[(long long)sd.z * STRIDE + lane * 2];
        float n0 = (kk + 0 < c) ? __int_as_float(sa.y) : 0.f;
        float n1 = (kk + 1 < c) ? __int_as_float(sa.w) : 0.f;
        float n2 = (kk + 2 < c) ? __int_as_float(sb.y) : 0.f;
        float n3 = (kk + 3 < c) ? __int_as_float(sb.w) : 0.f;
        float n4 = (kk + 4 < c) ? __int_as_float(sc.y) : 0.f;
        float n5 = (kk + 5 < c) ? __int_as_float(sc.w) : 0.f;
        float n6 = (kk + 6 < c) ? __int_as_float(sd.y) : 0.f;
        float n7 = (kk + 7 < c) ? __int_as_float(sd.w) : 0.f;
        float2 f0 = __half22float2(v0), f1 = __half22float2(v1);
        float2 f2 = __half22float2(v2), f3 = __half22float2(v3);
        float2 f4 = __half22float2(v4), f5 = __half22float2(v5);
        float2 f6 = __half22float2(v6), f7 = __half22float2(v7);
        acc.x = fmaf(n0, f0.x, acc.x); acc.y = fmaf(n0, f0.y, acc.y);
        acc.x = fmaf(n1, f1.x, acc.x); acc.y = fmaf(n1, f1.y, acc.y);
        acc.x = fmaf(n2, f2.x, acc.x); acc.y = fmaf(n2, f2.y, acc.y);
        acc.x = fmaf(n3, f3.x, acc.x); acc.y = fmaf(n3, f3.y, acc.y);
        acc.x = fmaf(n4, f4.x, acc.x); acc.y = fmaf(n4, f4.y, acc.y);
        acc.x = fmaf(n5, f5.x, acc.x); acc.y = fmaf(n5, f5.y, acc.y);
        acc.x = fmaf(n6, f6.x, acc.x); acc.y = fmaf(n6, f6.y, acc.y);
        acc.x = fmaf(n7, f7.x, acc.x); acc.y = fmaf(n7, f7.y, acc.y);
        sa = na; sb = nb; sc = nc_; sd = nd;
    }
    return acc;
}

// -------- GEMM1: g_h1h[N,64] = fp16(x[N,128] @ W1[128,64]) --------
__global__ void gemm1(const float* __restrict__ A, const float* __restrict__ B) {
    __shared__ __align__(16) float sA[64][68];
    __shared__ __align__(16) float sB[64][64];
    int tid = threadIdx.x;
    int tx = tid & 15, ty = tid >> 4;
    int row0 = blockIdx.x * 64;
    ull acc2[4][2] = {};

    for (int kc = 0; kc < 2; kc++) {
#pragma unroll
        for (int t = 0; t < 4; t++) {
            int lin = (t * 256 + tid) * 4;
            int r  = lin >> 6;
            int k0 = lin & 63;
            int grow = row0 + r;
            float4 v = make_float4(0.f, 0.f, 0.f, 0.f);
            if (grow < NN) v = *(const float4*)&A[(long long)grow * NF1 + kc * 64 + k0];
            *(float4*)&sA[r][k0] = v;
            float4 w = *(const float4*)&B[(kc * 64 + r) * NH + k0];
            *(float4*)&sB[r][k0] = w;
        }
        __syncthreads();
#pragma unroll
        for (int k = 0; k < 64; k++) {
            const ull* bp = (const ull*)&sB[k][tx * 4];
            ull b01 = bp[0];
            ull b23 = bp[1];
#pragma unroll
            for (int i = 0; i < 4; i++) {
                float a = sA[ty * 4 + i][k];
                ull pa = pack2(a, a);
                fma2(acc2[i][0], pa, b01);
                fma2(acc2[i][1], pa, b23);
            }
        }
        __syncthreads();
    }
#pragma unroll
    for (int i = 0; i < 4; i++) {
        int grow = row0 + ty * 4 + i;
        if (grow < NN) {
            __half2 h0 = __float22half2_rn(unpack2(acc2[i][0]));
            __half2 h1 = __float22half2_rn(unpack2(acc2[i][1]));
            uint2 st;
            st.x = *(unsigned*)&h0;
            st.y = *(unsigned*)&h1;
            *(uint2*)&g_h1h[(long long)grow * NH + tx * 4] = st;
        }
    }
}

// -------- FUSED gather1 + GEMM2: 512 threads, 16 warps x 4 nodes --------
__global__ void g1g2(const float* __restrict__ b1, const float* __restrict__ W2) {
    __shared__ __align__(16) float sA[64][68];    // out1 rows (fp32)
    __shared__ __align__(16) float sB[64 * 40];   // W2
    int tid = threadIdx.x;          // 0..511
    int warp = tid >> 5, lane = tid & 31;
    int row0 = blockIdx.x * 64;

    for (int idx = tid; idx < 64 * 40; idx += 512) sB[idx] = W2[idx];

    float bx = __ldg(&b1[lane * 2]);
    float by = __ldg(&b1[lane * 2 + 1]);

#pragma unroll
    for (int i = 0; i < 4; i++) {
        int r = warp * 4 + i;
        int node = row0 + r;
        float2 o = make_float2(0.f, 0.f);
        if (node < NN) {
            int c = min(g_cnt[node], CAP);
            float2 acc = gather_node<NH>(&g_slot[(long long)node * CAP], c, g_h1h, lane);
            float dc = rsqrtf(g_deg[node]);
            float2 self = __half22float2(*(const __half2*)&g_h1h[(long long)node * NH + lane * 2]);
            o.x = fmaxf(fmaf(dc, fmaf(dc, self.x, acc.x), bx), 0.f);
            o.y = fmaxf(fmaf(dc, fmaf(dc, self.y, acc.y), by), 0.f);
        }
        *(float2*)&sA[r][lane * 2] = o;
    }
    __syncthreads();

    if (tid < 160) {
        int tx = tid % 10, ty = tid / 10;
        ull acc2[4][2] = {};
#pragma unroll
        for (int k = 0; k < 64; k++) {
            const ull* bp = (const ull*)&sB[k * 40 + tx * 4];
            ull b01 = bp[0];
            ull b23 = bp[1];
#pragma unroll
            for (int i = 0; i < 4; i++) {
                float a = sA[ty * 4 + i][k];
                ull pa = pack2(a, a);
                fma2(acc2[i][0], pa, b01);
                fma2(acc2[i][1], pa, b23);
            }
        }
#pragma unroll
        for (int i = 0; i < 4; i++) {
            int grow = row0 + ty * 4 + i;
            if (grow < NN) {
                __half2 h0 = __float22half2_rn(unpack2(acc2[i][0]));
                __half2 h1 = __float22half2_rn(unpack2(acc2[i][1]));
                uint2 st;
                st.x = *(unsigned*)&h0;
                st.y = *(unsigned*)&h1;
                *(uint2*)&g_h2h[(long long)grow * NC + tx * 4] = st;
            }
        }
    }
}

// -------- gather layer 2: warp per node, lanes 0..19, pipelined --------
__global__ void gather2(const float* __restrict__ b2, float* __restrict__ out) {
    int node = blockIdx.x * 8 + (threadIdx.x >> 5);
    if (node >= NN) return;
    int lane = threadIdx.x & 31;
    if (lane >= 20) return;
    int c = min(g_cnt[node], CAP);
    float2 acc = gather_node<NC>(&g_slot[(long long)node * CAP], c, g_h2h, lane);
    float dc = rsqrtf(g_deg[node]);
    float2 self = __half22float2(*(const __half2*)&g_h2h[(long long)node * NC + lane * 2]);
    float2 o;
    o.x = fmaf(dc, fmaf(dc, self.x, acc.x), __ldg(&b2[lane * 2]));
    o.y = fmaf(dc, fmaf(dc, self.y, acc.y), __ldg(&b2[lane * 2 + 1]));
    *(float2*)&out[(long long)node * NC + lane * 2] = o;
}

extern "C" void kernel_launch(void* const* d_in, const int* in_sizes, int n_in,
                              void* d_out, int out_size) {
    const float* x  = (const float*)d_in[0];
    const int*   ei = (const int*)d_in[1];     // int32 (JAX default x64-disabled)
    const float* ew = (const float*)d_in[2];
    const float* W1 = (const float*)d_in[3];
    const float* b1 = (const float*)d_in[4];
    const float* W2 = (const float*)d_in[5];
    const float* b2 = (const float*)d_in[6];
    float* out = (float*)d_out;

    (void)in_sizes; (void)n_in; (void)out_size;

    static cudaStream_t s2 = nullptr;
    static cudaEvent_t eFork = nullptr, eJoin = nullptr;
    if (s2 == nullptr) {
        cudaStreamCreateWithFlags(&s2, cudaStreamNonBlocking);
        cudaEventCreateWithFlags(&eFork, cudaEventDisableTiming);
        cudaEventCreateWithFlags(&eJoin, cudaEventDisableTiming);
    }

    // Fork: gemm1 (x,W1 only) runs concurrently with edge preprocessing.
    cudaEventRecord(eFork, 0);
    cudaStreamWaitEvent(s2, eFork, 0);
    gemm1<<<(NN + 63) / 64, 256, 0, s2>>>(x, W1);
    cudaEventRecord(eJoin, s2);

    // stream 0: serial prep (fully hidden under gemm1).
    k_init<<<(NN + 255) / 256, 256>>>();
    k_deg<<<(NE + 255) / 256, 256>>>(ei, ew);
    k_place<<<(NE + 255) / 256, 256>>>(ei, ew);

    // Join, then the fused tail.
    cudaStreamWaitEvent(0, eJoin, 0);
    g1g2<<<(NN + 63) / 64, 512>>>(b1, W2);
    gather2<<<(NN + 7) / 8, 256>>>(b2, out);
}

// round 13
// speedup vs baseline: 1.0605x; 1.0605x over previous
#include <cuda_runtime.h>
#include <cuda_fp16.h>

#define NN 100000
#define NE 1600000
#define CAP 128
#define NF1 128
#define NH  64
#define NC  40

typedef unsigned long long ull;

// -------- scratch (device globals; no allocation allowed) --------
__device__ float  g_deg[NN];
__device__ int    g_cnt[NN];
__device__ int2   g_slot[(long long)NN * CAP];  // (src_row, float_bits(dinv[src]*w))
// zero-init invariant: slots >= cnt are NEVER written by any replay -> stay (0, 0.0f),
// so unmasked accumulation over padded groups adds exactly 0.
__device__ __half g_h1h[(long long)NN * NH];    // fp16(x @ W1)
__device__ __half g_h2h[(long long)NN * NC];    // fp16(out1 @ W2)

// -------- packed f32x2 helpers --------
__device__ __forceinline__ ull pack2(float x, float y) {
    ull r;
    asm("mov.b64 %0, {%1, %2};" : "=l"(r) : "f"(x), "f"(y));
    return r;
}
__device__ __forceinline__ void fma2(ull& d, ull a, ull b) {
    asm("fma.rn.f32x2 %0, %1, %2, %0;" : "+l"(d) : "l"(a), "l"(b));
}
__device__ __forceinline__ float2 unpack2(ull v) {
    float2 f;
    asm("mov.b64 {%0, %1}, %2;" : "=f"(f.x), "=f"(f.y) : "l"(v));
    return f;
}

// -------- prep kernels --------
__global__ void k_init() {
    int n = blockIdx.x * blockDim.x + threadIdx.x;
    if (n < NN) { g_deg[n] = 1.0f; g_cnt[n] = 0; }  // self-loop weight 1
}

__global__ void k_deg(const int* __restrict__ ei, const float* __restrict__ ew) {
    int e = blockIdx.x * blockDim.x + threadIdx.x;
    if (e < NE) {
        int c = ei[NE + e];
        if (c >= 0 && c < NN) atomicAdd(&g_deg[c], ew[e]);
    }
}

__global__ void k_place(const int* __restrict__ ei, const float* __restrict__ ew) {
    int e = blockIdx.x * blockDim.x + threadIdx.x;
    if (e >= NE) return;
    int r = ei[e];
    int c = ei[NE + e];
    if (r < 0 || r >= NN || c < 0 || c >= NN) return;
    float dr = rsqrtf(g_deg[r]);          // deg >= 1 always (self loop)
    float pnorm = dr * ew[e];             // dinv[c] factored out; applied in gather epilogue
    int pos = atomicAdd(&g_cnt[c], 1);
    if (pos < CAP) {
        int2 s;
        s.x = r;
        s.y = __float_as_int(pnorm);
        g_slot[(long long)c * CAP + pos] = s;
    }
}

// -------- lean unmasked gather: 12 loads, 8 FMA2, 32-bit addressing --------
// Padded slots are (0, 0.0f) -> contribute nothing; no masks needed.
template<int STRIDE_BYTES>
__device__ __forceinline__ float2 gather_node(const int2* __restrict__ slots, int c,
                                              const char* __restrict__ hbase, int laneByte) {
    ull acc = 0;   // packed (0.0f, 0.0f)
    for (int kk = 0; kk < c; kk += 8) {
        int4 sa = *(const int4*)&slots[kk];
        int4 sb = *(const int4*)&slots[kk + 2];
        int4 sc = *(const int4*)&slots[kk + 4];
        int4 sd = *(const int4*)&slots[kk + 6];
        __half2 v0 = *(const __half2*)(hbase + ((unsigned)sa.x * STRIDE_BYTES + laneByte));
        __half2 v1 = *(const __half2*)(hbase + ((unsigned)sa.z * STRIDE_BYTES + laneByte));
        __half2 v2 = *(const __half2*)(hbase + ((unsigned)sb.x * STRIDE_BYTES + laneByte));
        __half2 v3 = *(const __half2*)(hbase + ((unsigned)sb.z * STRIDE_BYTES + laneByte));
        __half2 v4 = *(const __half2*)(hbase + ((unsigned)sc.x * STRIDE_BYTES + laneByte));
        __half2 v5 = *(const __half2*)(hbase + ((unsigned)sc.z * STRIDE_BYTES + laneByte));
        __half2 v6 = *(const __half2*)(hbase + ((unsigned)sd.x * STRIDE_BYTES + laneByte));
        __half2 v7 = *(const __half2*)(hbase + ((unsigned)sd.z * STRIDE_BYTES + laneByte));
        float2 f0 = __half22float2(v0), f1 = __half22float2(v1);
        float2 f2 = __half22float2(v2), f3 = __half22float2(v3);
        float2 f4 = __half22float2(v4), f5 = __half22float2(v5);
        float2 f6 = __half22float2(v6), f7 = __half22float2(v7);
        float n0 = __int_as_float(sa.y), n1 = __int_as_float(sa.w);
        float n2 = __int_as_float(sb.y), n3 = __int_as_float(sb.w);
        float n4 = __int_as_float(sc.y), n5 = __int_as_float(sc.w);
        float n6 = __int_as_float(sd.y), n7 = __int_as_float(sd.w);
        fma2(acc, pack2(n0, n0), pack2(f0.x, f0.y));
        fma2(acc, pack2(n1, n1), pack2(f1.x, f1.y));
        fma2(acc, pack2(n2, n2), pack2(f2.x, f2.y));
        fma2(acc, pack2(n3, n3), pack2(f3.x, f3.y));
        fma2(acc, pack2(n4, n4), pack2(f4.x, f4.y));
        fma2(acc, pack2(n5, n5), pack2(f5.x, f5.y));
        fma2(acc, pack2(n6, n6), pack2(f6.x, f6.y));
        fma2(acc, pack2(n7, n7), pack2(f7.x, f7.y));
    }
    return unpack2(acc);
}

// -------- GEMM1: g_h1h[N,64] = fp16(x[N,128] @ W1[128,64]) --------
__global__ void gemm1(const float* __restrict__ A, const float* __restrict__ B) {
    __shared__ __align__(16) float sA[64][68];
    __shared__ __align__(16) float sB[64][64];
    int tid = threadIdx.x;
    int tx = tid & 15, ty = tid >> 4;
    int row0 = blockIdx.x * 64;
    ull acc2[4][2] = {};

    for (int kc = 0; kc < 2; kc++) {
#pragma unroll
        for (int t = 0; t < 4; t++) {
            int lin = (t * 256 + tid) * 4;
            int r  = lin >> 6;
            int k0 = lin & 63;
            int grow = row0 + r;
            float4 v = make_float4(0.f, 0.f, 0.f, 0.f);
            if (grow < NN) v = *(const float4*)&A[(long long)grow * NF1 + kc * 64 + k0];
            *(float4*)&sA[r][k0] = v;
            float4 w = *(const float4*)&B[(kc * 64 + r) * NH + k0];
            *(float4*)&sB[r][k0] = w;
        }
        __syncthreads();
#pragma unroll
        for (int k = 0; k < 64; k++) {
            const ull* bp = (const ull*)&sB[k][tx * 4];
            ull b01 = bp[0];
            ull b23 = bp[1];
#pragma unroll
            for (int i = 0; i < 4; i++) {
                float a = sA[ty * 4 + i][k];
                ull pa = pack2(a, a);
                fma2(acc2[i][0], pa, b01);
                fma2(acc2[i][1], pa, b23);
            }
        }
        __syncthreads();
    }
#pragma unroll
    for (int i = 0; i < 4; i++) {
        int grow = row0 + ty * 4 + i;
        if (grow < NN) {
            __half2 h0 = __float22half2_rn(unpack2(acc2[i][0]));
            __half2 h1 = __float22half2_rn(unpack2(acc2[i][1]));
            uint2 st;
            st.x = *(unsigned*)&h0;
            st.y = *(unsigned*)&h1;
            *(uint2*)&g_h1h[(long long)grow * NH + tx * 4] = st;
        }
    }
}

// -------- FUSED gather1 + GEMM2: 256 threads, 8 warps x 8 nodes --------
__global__ void g1g2(const float* __restrict__ b1, const float* __restrict__ W2) {
    __shared__ __align__(16) float sA[64][68];    // out1 rows (fp32)
    __shared__ __align__(16) float sB[64 * 40];   // W2
    int tid = threadIdx.x;          // 0..255
    int warp = tid >> 5, lane = tid & 31;
    int row0 = blockIdx.x * 64;
    const char* h1base = (const char*)g_h1h;
    int laneByte = lane * 4;

    for (int idx = tid; idx < 64 * 40; idx += 256) sB[idx] = W2[idx];

    float bx = __ldg(&b1[lane * 2]);
    float by = __ldg(&b1[lane * 2 + 1]);

#pragma unroll
    for (int i = 0; i < 8; i++) {
        int r = warp * 8 + i;
        int node = row0 + r;
        float2 o = make_float2(0.f, 0.f);
        if (node < NN) {
            int c = min(g_cnt[node], CAP);
            float2 acc = gather_node<NH * 2>(&g_slot[(long long)node * CAP], c, h1base, laneByte);
            float dc = rsqrtf(g_deg[node]);
            float2 self = __half22float2(*(const __half2*)(h1base + ((unsigned)node * (NH * 2) + laneByte)));
            o.x = fmaxf(fmaf(dc, fmaf(dc, self.x, acc.x), bx), 0.f);
            o.y = fmaxf(fmaf(dc, fmaf(dc, self.y, acc.y), by), 0.f);
        }
        *(float2*)&sA[r][lane * 2] = o;
    }
    __syncthreads();

    if (tid < 160) {
        int tx = tid % 10, ty = tid / 10;
        ull acc2[4][2] = {};
#pragma unroll
        for (int k = 0; k < 64; k++) {
            const ull* bp = (const ull*)&sB[k * 40 + tx * 4];
            ull b01 = bp[0];
            ull b23 = bp[1];
#pragma unroll
            for (int i = 0; i < 4; i++) {
                float a = sA[ty * 4 + i][k];
                ull pa = pack2(a, a);
                fma2(acc2[i][0], pa, b01);
                fma2(acc2[i][1], pa, b23);
            }
        }
#pragma unroll
        for (int i = 0; i < 4; i++) {
            int grow = row0 + ty * 4 + i;
            if (grow < NN) {
                __half2 h0 = __float22half2_rn(unpack2(acc2[i][0]));
                __half2 h1 = __float22half2_rn(unpack2(acc2[i][1]));
                uint2 st;
                st.x = *(unsigned*)&h0;
                st.y = *(unsigned*)&h1;
                *(uint2*)&g_h2h[(long long)grow * NC + tx * 4] = st;
            }
        }
    }
}

// -------- gather layer 2: warp per node, lanes 0..19 --------
__global__ void gather2(const float* __restrict__ b2, float* __restrict__ out) {
    int node = blockIdx.x * 8 + (threadIdx.x >> 5);
    if (node >= NN) return;
    int lane = threadIdx.x & 31;
    if (lane >= 20) return;
    int c = min(g_cnt[node], CAP);
    const char* h2base = (const char*)g_h2h;
    int laneByte = lane * 4;
    float2 acc = gather_node<NC * 2>(&g_slot[(long long)node * CAP], c, h2base, laneByte);
    float dc = rsqrtf(g_deg[node]);
    float2 self = __half22float2(*(const __half2*)(h2base + ((unsigned)node * (NC * 2) + laneByte)));
    float2 o;
    o.x = fmaf(dc, fmaf(dc, self.x, acc.x), __ldg(&b2[lane * 2]));
    o.y = fmaf(dc, fmaf(dc, self.y, acc.y), __ldg(&b2[lane * 2 + 1]));
    *(float2*)&out[(long long)node * NC + lane * 2] = o;
}

extern "C" void kernel_launch(void* const* d_in, const int* in_sizes, int n_in,
                              void* d_out, int out_size) {
    const float* x  = (const float*)d_in[0];
    const int*   ei = (const int*)d_in[1];     // int32 (JAX default x64-disabled)
    const float* ew = (const float*)d_in[2];
    const float* W1 = (const float*)d_in[3];
    const float* b1 = (const float*)d_in[4];
    const float* W2 = (const float*)d_in[5];
    const float* b2 = (const float*)d_in[6];
    float* out = (float*)d_out;

    (void)in_sizes; (void)n_in; (void)out_size;

    static cudaStream_t s2 = nullptr;
    static cudaEvent_t eFork = nullptr, eJoin = nullptr;
    if (s2 == nullptr) {
        cudaStreamCreateWithFlags(&s2, cudaStreamNonBlocking);
        cudaEventCreateWithFlags(&eFork, cudaEventDisableTiming);
        cudaEventCreateWithFlags(&eJoin, cudaEventDisableTiming);
    }

    // Fork: gemm1 (x,W1 only) runs concurrently with edge preprocessing.
    cudaEventRecord(eFork, 0);
    cudaStreamWaitEvent(s2, eFork, 0);
    gemm1<<<(NN + 63) / 64, 256, 0, s2>>>(x, W1);
    cudaEventRecord(eJoin, s2);

    // stream 0: serial prep (fully hidden under gemm1).
    k_init<<<(NN + 255) / 256, 256>>>();
    k_deg<<<(NE + 255) / 256, 256>>>(ei, ew);
    k_place<<<(NE + 255) / 256, 256>>>(ei, ew);

    // Join, then the fused tail.
    cudaStreamWaitEvent(0, eJoin, 0);
    g1g2<<<(NN + 63) / 64, 256>>>(b1, W2);
    gather2<<<(NN + 7) / 8, 256>>>(b2, out);
}